// round 1
// baseline (speedup 1.0000x reference)
#include <cuda_runtime.h>

// DihedralToCartesian: B=65536 independent chains, N=126 sequential extension steps.
// Thread = one batch. CTA = 128 consecutive batches. Angle tiles and output tiles
// staged through shared memory for coalesced global traffic.

#define TPB      128
#define NRES     126
#define CHUNK    18            // divisible by 3 -> alpha/bond constants compile-time
#define NCHUNK   (NRES / CHUNK)
#define SIN_PITCH 19           // gcd(19,32)=1 -> conflict-free per-thread row reads
#define OUT_PITCH 55           // 18*3=54 payload, pad to 55 (gcd(55,32)=1)

__device__ __forceinline__ float frsqrt(float x) {
    float y;
    asm("rsqrt.approx.f32 %0, %1;" : "=f"(y) : "f"(x));
    return y;
}

__global__ void __launch_bounds__(TPB)
dihedral_kernel(const float* __restrict__ angles,
                const float* __restrict__ prev,
                float* __restrict__ out)
{
    __shared__ float s_sin[TPB * SIN_PITCH];
    __shared__ float s_cos[TPB * SIN_PITCH];
    __shared__ float s_out[TPB * OUT_PITCH];

    const int tid   = threadIdx.x;
    const int Bbase = blockIdx.x * TPB;

    // rotation constants: rot0 = bond*cos(alpha), rs = bond*sin(alpha), period 3
    float R0[3], RS[3];
    {
        const float alpha[3] = {2.028f, 2.124f, 1.941f};
        const float bond [3] = {1.329f, 1.458f, 1.523f};
        #pragma unroll
        for (int k = 0; k < 3; ++k) {
            R0[k] = bond[k] * cosf(alpha[k]);
            RS[k] = bond[k] * sinf(alpha[k]);
        }
    }

    // carry (a, b, c) from prev_three[b, 0..2, :]
    const float* p = prev + (size_t)(Bbase + tid) * 9;
    float ax = p[0], ay = p[1], az = p[2];
    float bx = p[3], by = p[4], bz = p[5];
    float cx = p[6], cy = p[7], cz = p[8];

    const float* gang = angles + (size_t)Bbase * (2 * NRES);
    float*       gout = out    + (size_t)Bbase * (NRES * 3);

    for (int ch = 0; ch < NCHUNK; ++ch) {
        const int i0 = ch * CHUNK;

        // ---- cooperative coalesced load of sin/cos tiles ----
        #pragma unroll
        for (int e = tid; e < TPB * CHUNK; e += TPB) {
            int r = e / CHUNK;
            int q = e - r * CHUNK;
            s_sin[r * SIN_PITCH + q] = gang[r * (2 * NRES) + i0 + q];
            s_cos[r * SIN_PITCH + q] = gang[r * (2 * NRES) + NRES + i0 + q];
        }
        __syncthreads();

        // ---- 18 sequential extension steps ----
        const float* ms = &s_sin[tid * SIN_PITCH];
        const float* mc = &s_cos[tid * SIN_PITCH];
        float*       mo = &s_out[tid * OUT_PITCH];

        #pragma unroll
        for (int j = 0; j < CHUNK; ++j) {
            const int k = j % 3;   // compile-time under full unroll (i0 % 3 == 0)
            float s  = ms[j];
            float co = mc[j];

            // normalize (sin, cos): n = sqrt(s^2 + c^2 + 1e-8)
            float invn = frsqrt(fmaf(s, s, fmaf(co, co, 1e-8f)));
            float t    = RS[k] * invn;
            float rot0 = R0[k];
            float rot1 =  t * co;
            float rot2 = -t * s;

            // bc = normalize((b - c) + 1e-8)
            float bcx = (bx - cx) + 1e-8f;
            float bcy = (by - cy) + 1e-8f;
            float bcz = (bz - cz) + 1e-8f;
            float ib = frsqrt(fmaf(bcx, bcx, fmaf(bcy, bcy, bcz * bcz)));
            bcx *= ib; bcy *= ib; bcz *= ib;

            // n = normalize(cross(b - a, bc) + 1e-8)
            float vx = bx - ax, vy = by - ay, vz = bz - az;
            float nx = fmaf(vy, bcz, fmaf(-vz, bcy, 1e-8f));
            float ny = fmaf(vz, bcx, fmaf(-vx, bcz, 1e-8f));
            float nz = fmaf(vx, bcy, fmaf(-vy, bcx, 1e-8f));
            float in_ = frsqrt(fmaf(nx, nx, fmaf(ny, ny, nz * nz)));
            nx *= in_; ny *= in_; nz *= in_;

            // m1 = cross(n, bc)
            float mx = ny * bcz - nz * bcy;
            float my = nz * bcx - nx * bcz;
            float mz = nx * bcy - ny * bcx;

            // d = c + rot0*bc + rot1*m1 + rot2*n
            float dx = fmaf(rot2, nx, fmaf(rot1, mx, fmaf(rot0, bcx, cx)));
            float dy = fmaf(rot2, ny, fmaf(rot1, my, fmaf(rot0, bcy, cy)));
            float dz = fmaf(rot2, nz, fmaf(rot1, mz, fmaf(rot0, bcz, cz)));

            mo[j * 3 + 0] = dx;
            mo[j * 3 + 1] = dy;
            mo[j * 3 + 2] = dz;

            // shift carry
            ax = bx; ay = by; az = bz;
            bx = cx; by = cy; bz = cz;
            cx = dx; cy = dy; cz = dz;
        }
        __syncthreads();

        // ---- cooperative coalesced store of output tile ----
        #pragma unroll
        for (int e = tid; e < TPB * CHUNK * 3; e += TPB) {
            int r = e / (CHUNK * 3);
            int q = e - r * (CHUNK * 3);
            gout[r * (NRES * 3) + i0 * 3 + q] = s_out[r * OUT_PITCH + q];
        }
        __syncthreads();
    }
}

extern "C" void kernel_launch(void* const* d_in, const int* in_sizes, int n_in,
                              void* d_out, int out_size)
{
    const float* angles = (const float*)d_in[0];   // (B, 252) f32
    const float* prev   = (const float*)d_in[1];   // (B, 3, 3) f32
    float*       out    = (float*)d_out;           // (B, 126, 3) f32

    const int B = in_sizes[0] / (2 * NRES);        // 65536
    dihedral_kernel<<<B / TPB, TPB>>>(angles, prev, out);
}